// round 13
// baseline (speedup 1.0000x reference)
#include <cuda_runtime.h>
#include <cuda_bf16.h>
#include <cstdint>

// Problem constants
#define NB 4
#define NC 64
#define NHH 256
#define NWW 256
#define NH 63
#define NW 63
#define LPB (NH*NW)        // 3969
#define M_TOT (NB*LPB)     // 15876
#define M_PAD 16000
#define KDIM 4096
#define HID 256
#define TOT ((size_t)NB*NC*NHH*NWW)   // 16777216

// Scratch (static device globals)
static __device__ __nv_bfloat16 g_W1b[(size_t)HID*KDIM];     // 2 MB
static __device__ __nv_bfloat16 g_W2b[(size_t)KDIM*HID];     // 2 MB
static __device__ __nv_bfloat16 g_xb[(size_t)TOT];           // 32 MB
static __device__ __nv_bfloat16 g_G[(size_t)M_PAD*HID];      // 8 MB
static __device__ __nv_bfloat16 g_img[(size_t)4*TOT];        // 134 MB
static __device__ float g_alpha;

// ---------------------------------------------------------------------------
// mma / cp.async helpers
// ---------------------------------------------------------------------------
__device__ __forceinline__ void ldm4(uint32_t& r0, uint32_t& r1, uint32_t& r2, uint32_t& r3, uint32_t a){
  asm volatile("ldmatrix.sync.aligned.m8n8.x4.shared.b16 {%0,%1,%2,%3},[%4];\n"
    : "=r"(r0), "=r"(r1), "=r"(r2), "=r"(r3) : "r"(a));
}
__device__ __forceinline__ void mma_bf16(float* d, const uint32_t* a, const uint32_t* b){
  asm volatile("mma.sync.aligned.m16n8k16.row.col.f32.bf16.bf16.f32 "
    "{%0,%1,%2,%3},{%4,%5,%6,%7},{%8,%9},{%0,%1,%2,%3};\n"
    : "+f"(d[0]), "+f"(d[1]), "+f"(d[2]), "+f"(d[3])
    : "r"(a[0]), "r"(a[1]), "r"(a[2]), "r"(a[3]), "r"(b[0]), "r"(b[1]));
}
// 16B cp.async (requires 16B-aligned src)
__device__ __forceinline__ void cpa16(uint32_t dst, const void* src, uint32_t sz){
  asm volatile("cp.async.cg.shared.global [%0], [%1], 16, %2;\n"
    :: "r"(dst), "l"(src), "r"(sz) : "memory");
}
// 8B cp.async (requires only 8B-aligned src) — for the im2col A path (pw*8 B offsets)
__device__ __forceinline__ void cpa8(uint32_t dst, const void* src, uint32_t sz){
  asm volatile("cp.async.ca.shared.global [%0], [%1], 8, %2;\n"
    :: "r"(dst), "l"(src), "r"(sz) : "memory");
}
#define CP_COMMIT() asm volatile("cp.async.commit_group;\n" ::: "memory")
#define CP_WAIT2()  asm volatile("cp.async.wait_group 2;\n" ::: "memory")
#define CP_WAIT0()  asm volatile("cp.async.wait_group 0;\n" ::: "memory")

// smem tile: rows x 4 chunks of 16B (BK=32 bf16). XOR swizzle: conflict-free ldmatrix.
__device__ __forceinline__ int sw_idx(int row, int ch){ return row*4 + (ch ^ ((row>>1)&3)); }

// Pipeline geometry: stage = [A: 64 rows x 64B = 4KB][B: 256 rows x 64B = 16KB]
#define STG 20480
#define NST 4
#define DSM (STG*NST)   // 80 KB dynamic smem; 2 CTAs/SM = 160 KB
// C-staging layout inside dsm (reused after mainloop): 64 rows x 528B stride
#define CSTRIDE 528

// One BK=32 slab per warp: 2 k16 steps, warp tile 32(M) x 64(N).
// Block tile: BM=64 (wm in {0,1}), BN=256 (wn in {0..3}).
__device__ __forceinline__ void compute_tile(uint32_t baseA, uint32_t baseB,
                                             int wm, int wn, int lane, float (*acc)[8][4]){
  #pragma unroll
  for (int ks = 0; ks < 2; ks++){
    uint32_t afr[2][4], bfr[8][2];
    #pragma unroll
    for (int mt = 0; mt < 2; mt++){
      int row = wm*32 + mt*16 + (lane & 15);
      int ch  = ks*2 + (lane >> 4);
      ldm4(afr[mt][0], afr[mt][1], afr[mt][2], afr[mt][3], baseA + (sw_idx(row, ch) << 4));
    }
    #pragma unroll
    for (int ntp = 0; ntp < 4; ntp++){
      int g   = lane >> 3;
      int row = wn*64 + ntp*16 + (g >> 1)*8 + (lane & 7);
      int ch  = ks*2 + (g & 1);
      ldm4(bfr[ntp*2][0], bfr[ntp*2][1], bfr[ntp*2+1][0], bfr[ntp*2+1][1],
           baseB + (sw_idx(row, ch) << 4));
    }
    #pragma unroll
    for (int mt = 0; mt < 2; mt++)
      #pragma unroll
      for (int nt = 0; nt < 8; nt++)
        mma_bf16(acc[mt][nt], afr[mt], bfr[nt]);
  }
}

// ---------------------------------------------------------------------------
// K0a: weights fp32 -> bf16 + alpha
// ---------------------------------------------------------------------------
__global__ void k_convert(const float* __restrict__ W1, const float* __restrict__ W2,
                          const float* __restrict__ alpha_raw){
  int t = blockIdx.x*blockDim.x + threadIdx.x;
  if (t == 0) g_alpha = log1pf(expf(alpha_raw[0]));
  if (t < HID*KDIM/4){
    float4 a = ((const float4*)W1)[t];
    float4 b = ((const float4*)W2)[t];
    uint2 pa, pb;
    *(__nv_bfloat162*)&pa.x = __floats2bfloat162_rn(a.x, a.y);
    *(__nv_bfloat162*)&pa.y = __floats2bfloat162_rn(a.z, a.w);
    *(__nv_bfloat162*)&pb.x = __floats2bfloat162_rn(b.x, b.y);
    *(__nv_bfloat162*)&pb.y = __floats2bfloat162_rn(b.z, b.w);
    ((uint2*)g_W1b)[t] = pa;
    ((uint2*)g_W2b)[t] = pb;
  }
}

// K0b: x fp32 -> bf16
__global__ void k_convx(const float* __restrict__ x){
  size_t t = (size_t)blockIdx.x*blockDim.x + threadIdx.x;
  if (t < TOT/4){
    float4 a = ((const float4*)x)[t];
    uint2 p;
    *(__nv_bfloat162*)&p.x = __floats2bfloat162_rn(a.x, a.y);
    *(__nv_bfloat162*)&p.y = __floats2bfloat162_rn(a.z, a.w);
    ((uint2*)g_xb)[t] = p;
  }
}

// ---------------------------------------------------------------------------
// K1: GEMM1 (implicit im2col, cp.async 4-stage) + bias + GELU -> G bf16
//     block 64(M) x 256(N), K=4096 in 128 slabs of 32. Staged coalesced epilogue.
// ---------------------------------------------------------------------------
__global__ void __launch_bounds__(256, 2) k_gemm1(const float* __restrict__ b1){
  extern __shared__ char dsm[];
  const uint32_t sbase = (uint32_t)__cvta_generic_to_shared(dsm);
  const int tid  = threadIdx.x;
  const int lane = tid & 31, warp = tid >> 5;
  const int wm = warp & 1, wn = warp >> 1;
  const int l0 = blockIdx.x * 64;

  const int rr = tid >> 2, ch = tid & 3;
  const int l = l0 + rr;
  const bool av = (l < M_TOT);
  const uint32_t asz = av ? 8u : 0u;
  int bb = 0, ph = 0, pw = 0;
  if (av){ bb = l / LPB; int rem = l - bb*LPB; ph = rem / NW; pw = rem - ph*NW; }
  const __nv_bfloat16* xb = g_xb + (size_t)bb*(NC*65536) + (size_t)(ph*4)*256 + pw*4;
  const __nv_bfloat16* wp[4];
  #pragma unroll
  for (int q = 0; q < 4; q++) wp[q] = g_W1b + (size_t)(rr + 64*q)*KDIM + ch*8;
  const uint32_t adst = (uint32_t)(sw_idx(rr, ch) << 4);
  uint32_t bdst[4];
  #pragma unroll
  for (int q = 0; q < 4; q++) bdst[q] = 4096u + (uint32_t)(sw_idx(rr + 64*q, ch) << 4);

  const int KT = KDIM / 32;  // 128
  // prologue: stages 0..2
  #pragma unroll
  for (int kt = 0; kt < 3; kt++){
    uint32_t sb = sbase + (uint32_t)kt*STG;
    int k = kt*32 + ch*8;
    const __nv_bfloat16* asrc = xb + (k >> 6)*65536 + ((k >> 3) & 7)*256;
    cpa8(sb + adst,      asrc,     asz);   // 8B-aligned src (pw*8 B)
    cpa8(sb + adst + 8u, asrc + 4, asz);
    #pragma unroll
    for (int q = 0; q < 4; q++) cpa16(sb + bdst[q], wp[q] + kt*32, 16u);
    CP_COMMIT();
  }

  float acc[2][8][4];
  #pragma unroll
  for (int a = 0; a < 2; a++)
    #pragma unroll
    for (int b = 0; b < 8; b++)
      #pragma unroll
      for (int c = 0; c < 4; c++) acc[a][b][c] = 0.f;

  for (int kt = 0; kt < KT; kt++){
    if (kt + 2 < KT) CP_WAIT2(); else CP_WAIT0();
    __syncthreads();
    uint32_t sb = sbase + (uint32_t)(kt & 3)*STG;
    compute_tile(sb, sb + 4096u, wm, wn, lane, acc);
    int kn = kt + 3;
    if (kn < KT){
      uint32_t sn = sbase + (uint32_t)(kn & 3)*STG;
      int k = kn*32 + ch*8;
      const __nv_bfloat16* asrc = xb + (k >> 6)*65536 + ((k >> 3) & 7)*256;
      cpa8(sn + adst,      asrc,     asz);
      cpa8(sn + adst + 8u, asrc + 4, asz);
      #pragma unroll
      for (int q = 0; q < 4; q++) cpa16(sn + bdst[q], wp[q] + kn*32, 16u);
      CP_COMMIT();
    }
  }

  // epilogue: bias + exact GELU -> stage C in smem, then coalesced rows to g_G
  __syncthreads();   // all warps done reading pipeline stages before reuse
  #pragma unroll
  for (int mt = 0; mt < 2; mt++){
    #pragma unroll
    for (int hf = 0; hf < 2; hf++){
      int r = wm*32 + mt*16 + (lane >> 2) + hf*8;
      #pragma unroll
      for (int nt = 0; nt < 8; nt++){
        int n = wn*64 + nt*8 + (lane & 3)*2;
        float v0 = acc[mt][nt][hf*2+0] + b1[n];
        float v1 = acc[mt][nt][hf*2+1] + b1[n+1];
        v0 = 0.5f*v0*(1.f + erff(v0*0.70710678118654752f));
        v1 = 0.5f*v1*(1.f + erff(v1*0.70710678118654752f));
        *(__nv_bfloat162*)(dsm + r*CSTRIDE + n*2) = __floats2bfloat162_rn(v0, v1);
      }
    }
  }
  __syncthreads();
  // warp w stores rows w, w+8, ..., w+56 as full 512B coalesced rows
  #pragma unroll
  for (int q = 0; q < 8; q++){
    int r = q*8 + warp;
    uint4 v = *(uint4*)(dsm + r*CSTRIDE + lane*16);
    *(uint4*)((char*)(g_G + (size_t)(l0 + r)*HID) + lane*16) = v;
  }
}

// ---------------------------------------------------------------------------
// K2: GEMM2 (cp.async 4-stage) -> bias; stage C in smem, coalesced 8B scatter
//     block 64(M) x 256(N of 4096), K=256 in 8 slabs of 32
// ---------------------------------------------------------------------------
__global__ void __launch_bounds__(256, 2) k_gemm2(const float* __restrict__ b2){
  extern __shared__ char dsm[];
  const uint32_t sbase = (uint32_t)__cvta_generic_to_shared(dsm);
  const int tid  = threadIdx.x;
  const int lane = tid & 31, warp = tid >> 5;
  const int wm = warp & 1, wn = warp >> 1;
  const int l0 = blockIdx.y * 64;
  const int n0 = blockIdx.x * 256;

  const int rr = tid >> 2, ch = tid & 3;
  const __nv_bfloat16* ga = g_G + (size_t)(l0 + rr)*HID + ch*8;   // rows < 16000 always valid
  const __nv_bfloat16* wp[4];
  #pragma unroll
  for (int q = 0; q < 4; q++) wp[q] = g_W2b + (size_t)(n0 + rr + 64*q)*HID + ch*8;
  const uint32_t adst = (uint32_t)(sw_idx(rr, ch) << 4);
  uint32_t bdst[4];
  #pragma unroll
  for (int q = 0; q < 4; q++) bdst[q] = 4096u + (uint32_t)(sw_idx(rr + 64*q, ch) << 4);

  const int KT = HID / 32;  // 8
  #pragma unroll
  for (int kt = 0; kt < 3; kt++){
    uint32_t sb = sbase + (uint32_t)kt*STG;
    cpa16(sb + adst, ga + kt*32, 16u);
    #pragma unroll
    for (int q = 0; q < 4; q++) cpa16(sb + bdst[q], wp[q] + kt*32, 16u);
    CP_COMMIT();
  }

  float acc[2][8][4];
  #pragma unroll
  for (int a = 0; a < 2; a++)
    #pragma unroll
    for (int b = 0; b < 8; b++)
      #pragma unroll
      for (int c = 0; c < 4; c++) acc[a][b][c] = 0.f;

  for (int kt = 0; kt < KT; kt++){
    if (kt + 2 < KT) CP_WAIT2(); else CP_WAIT0();
    __syncthreads();
    uint32_t sb = sbase + (uint32_t)(kt & 3)*STG;
    compute_tile(sb, sb + 4096u, wm, wn, lane, acc);
    int kn = kt + 3;
    if (kn < KT){
      uint32_t sn = sbase + (uint32_t)(kn & 3)*STG;
      cpa16(sn + adst, ga + kn*32, 16u);
      #pragma unroll
      for (int q = 0; q < 4; q++) cpa16(sn + bdst[q], wp[q] + kn*32, 16u);
      CP_COMMIT();
    }
  }

  // stage C (+bias) into smem [64 rows][CSTRIDE]
  __syncthreads();   // pipeline stages dead before smem reuse
  #pragma unroll
  for (int mt = 0; mt < 2; mt++){
    #pragma unroll
    for (int hf = 0; hf < 2; hf++){
      int r = wm*32 + mt*16 + (lane >> 2) + hf*8;
      #pragma unroll
      for (int nt = 0; nt < 8; nt++){
        int nl = wn*64 + nt*8 + (lane & 3)*2;
        float v0 = acc[mt][nt][hf*2+0] + b2[n0 + nl];
        float v1 = acc[mt][nt][hf*2+1] + b2[n0 + nl + 1];
        *(__nv_bfloat162*)(dsm + r*CSTRIDE + nl*2) = __floats2bfloat162_rn(v0, v1);
      }
    }
  }
  __syncthreads();

  // coalesced scatter: thread -> patch l (tid&63), combos (tid>>6 + q*4)
  {
    int li = tid & 63;
    int sub = tid >> 6;
    int l = l0 + li;
    if (l < M_TOT){
      int bb = l / LPB; int rem = l - bb*LPB;
      int ph = rem / NW; int pw = rem - ph*NW;
      const int Cbase = n0 >> 6;   // global channel base (n0 multiple of 256)
      #pragma unroll
      for (int q = 0; q < 16; q++){
        int idx = sub + q*4;        // 0..63
        int c   = idx >> 4;         // 0..3
        int kh  = (idx >> 1) & 7;   // 0..7
        int dw  = idx & 1;          // kw quad select
        int nl  = c*64 + kh*8 + dw*4;
        uint2 v = *(const uint2*)(dsm + li*CSTRIDE + nl*2);
        int dlt = ((kh >> 2) << 1) | dw;
        int i   = ph*4 + kh;
        int jb  = pw*4 + dw*4;
        size_t off = (size_t)dlt*TOT + (size_t)bb*4194304
                   + (size_t)(Cbase + c)*65536 + (size_t)i*256 + jb;
        *(uint2*)(g_img + off) = v;   // 4 bf16, 8B aligned, consecutive-l coalesced
      }
    }
  }
}

// ---------------------------------------------------------------------------
// K3: blend  out = x + alpha * (sum of valid phase images)/norm  (x4 vectorized)
// ---------------------------------------------------------------------------
__global__ void k_blend(const float* __restrict__ x, float* __restrict__ out){
  size_t t = (size_t)blockIdx.x*blockDim.x + threadIdx.x;
  if (t >= TOT/4) return;
  size_t e = t*4;
  int j0 = (int)(e & 255);
  int i  = (int)((e >> 8) & 255);
  bool h0 = (i <= 251), h1 = (i >= 4), w0 = (j0 < 252), w1 = (j0 >= 4);

  float4 xv = *(const float4*)(x + e);
  float s0 = 0.f, s1 = 0.f, s2 = 0.f, s3 = 0.f;
  #pragma unroll
  for (int d = 0; d < 4; d++){
    bool v = (d == 0) ? (h0 && w0) : (d == 1) ? (h0 && w1) : (d == 2) ? (h1 && w0) : (h1 && w1);
    if (v){
      uint2 p = *(const uint2*)(g_img + (size_t)d*TOT + e);
      float2 f0 = __bfloat1622float2(*(const __nv_bfloat162*)&p.x);
      float2 f1 = __bfloat1622float2(*(const __nv_bfloat162*)&p.y);
      s0 += f0.x; s1 += f0.y; s2 += f1.x; s3 += f1.y;
    }
  }
  float scale = g_alpha * (((h0 && h1) ? 0.5f : 1.0f) * ((w0 && w1) ? 0.5f : 1.0f));
  float4 ov;
  ov.x = xv.x + scale * s0;
  ov.y = xv.y + scale * s1;
  ov.z = xv.z + scale * s2;
  ov.w = xv.w + scale * s3;
  *(float4*)(out + e) = ov;
}

// ---------------------------------------------------------------------------
extern "C" void kernel_launch(void* const* d_in, const int* in_sizes, int n_in,
                              void* d_out, int out_size){
  (void)in_sizes; (void)n_in; (void)out_size;
  const float* x         = (const float*)d_in[0];
  const float* W1        = (const float*)d_in[1];
  const float* b1        = (const float*)d_in[2];
  const float* W2        = (const float*)d_in[3];
  const float* b2        = (const float*)d_in[4];
  const float* alpha_raw = (const float*)d_in[5];
  float* out = (float*)d_out;

  // host-side attribute set (not an allocation; unconditional & deterministic)
  cudaFuncSetAttribute(k_gemm1, cudaFuncAttributeMaxDynamicSharedMemorySize, DSM);
  cudaFuncSetAttribute(k_gemm2, cudaFuncAttributeMaxDynamicSharedMemorySize, DSM);

  k_convert<<<(HID*KDIM/4 + 255)/256, 256>>>(W1, W2, alpha_raw);
  k_convx<<<(int)((TOT/4 + 255)/256), 256>>>(x);
  k_gemm1<<<250, 256, DSM>>>(b1);
  k_gemm2<<<dim3(16, 250), 256, DSM>>>(b2);
  k_blend<<<(int)((TOT/4 + 255)/256), 256>>>(x, out);
}

// round 15
// speedup vs baseline: 1.0591x; 1.0591x over previous
#include <cuda_runtime.h>
#include <cuda_bf16.h>
#include <cstdint>

// Problem constants
#define NB 4
#define NC 64
#define NHH 256
#define NWW 256
#define NH 63
#define NW 63
#define LPB (NH*NW)        // 3969
#define M_TOT (NB*LPB)     // 15876
#define M_PAD 16000
#define KDIM 4096
#define HID 256
#define TOT ((size_t)NB*NC*NHH*NWW)   // 16777216

// Scratch (static device globals)
static __device__ __nv_bfloat16 g_W1b[(size_t)HID*KDIM];     // 2 MB
static __device__ __nv_bfloat16 g_W2b[(size_t)KDIM*HID];     // 2 MB
static __device__ __nv_bfloat16 g_xb[(size_t)TOT];           // 32 MB
static __device__ __nv_bfloat16 g_G[(size_t)M_PAD*HID];      // 8 MB
static __device__ __nv_bfloat16 g_img[(size_t)4*TOT];        // 134 MB
static __device__ float g_alpha;

// ---------------------------------------------------------------------------
// mma / cp.async helpers
// ---------------------------------------------------------------------------
__device__ __forceinline__ void ldm4(uint32_t& r0, uint32_t& r1, uint32_t& r2, uint32_t& r3, uint32_t a){
  asm volatile("ldmatrix.sync.aligned.m8n8.x4.shared.b16 {%0,%1,%2,%3},[%4];\n"
    : "=r"(r0), "=r"(r1), "=r"(r2), "=r"(r3) : "r"(a));
}
__device__ __forceinline__ void mma_bf16(float* d, const uint32_t* a, const uint32_t* b){
  asm volatile("mma.sync.aligned.m16n8k16.row.col.f32.bf16.bf16.f32 "
    "{%0,%1,%2,%3},{%4,%5,%6,%7},{%8,%9},{%0,%1,%2,%3};\n"
    : "+f"(d[0]), "+f"(d[1]), "+f"(d[2]), "+f"(d[3])
    : "r"(a[0]), "r"(a[1]), "r"(a[2]), "r"(a[3]), "r"(b[0]), "r"(b[1]));
}
// 16B cp.async (requires 16B-aligned src)
__device__ __forceinline__ void cpa16(uint32_t dst, const void* src, uint32_t sz){
  asm volatile("cp.async.cg.shared.global [%0], [%1], 16, %2;\n"
    :: "r"(dst), "l"(src), "r"(sz) : "memory");
}
// 8B cp.async (requires only 8B-aligned src) — for the im2col A path (pw*8 B offsets)
__device__ __forceinline__ void cpa8(uint32_t dst, const void* src, uint32_t sz){
  asm volatile("cp.async.ca.shared.global [%0], [%1], 8, %2;\n"
    :: "r"(dst), "l"(src), "r"(sz) : "memory");
}
#define CP_COMMIT() asm volatile("cp.async.commit_group;\n" ::: "memory")
#define CP_WAIT2()  asm volatile("cp.async.wait_group 2;\n" ::: "memory")
#define CP_WAIT0()  asm volatile("cp.async.wait_group 0;\n" ::: "memory")

// smem tile: rows x 4 chunks of 16B (BK=32 bf16). XOR swizzle: conflict-free ldmatrix.
__device__ __forceinline__ int sw_idx(int row, int ch){ return row*4 + (ch ^ ((row>>1)&3)); }

// Pipeline geometry: stage = [A: 64 rows x 64B = 4KB][B: 256 rows x 64B = 16KB]
#define STG 20480
#define NST 4
#define DSM (STG*NST)   // 80 KB dynamic smem; 2 CTAs/SM = 160 KB

// One BK=32 slab per warp: 2 k16 steps, warp tile 64(M) x 64(N).
// Block tile: BM=64, BN=256; 4 warps, warp wn owns cols wn*64..wn*64+63, all 64 rows.
__device__ __forceinline__ void compute_tile(uint32_t baseA, uint32_t baseB,
                                             int wn, int lane, float (*acc)[8][4]){
  #pragma unroll
  for (int ks = 0; ks < 2; ks++){
    uint32_t afr[4][4], bfr[8][2];
    #pragma unroll
    for (int mt = 0; mt < 4; mt++){
      int row = mt*16 + (lane & 15);
      int ch  = ks*2 + (lane >> 4);
      ldm4(afr[mt][0], afr[mt][1], afr[mt][2], afr[mt][3], baseA + (sw_idx(row, ch) << 4));
    }
    #pragma unroll
    for (int ntp = 0; ntp < 4; ntp++){
      int g   = lane >> 3;
      int row = wn*64 + ntp*16 + (g >> 1)*8 + (lane & 7);
      int ch  = ks*2 + (g & 1);
      ldm4(bfr[ntp*2][0], bfr[ntp*2][1], bfr[ntp*2+1][0], bfr[ntp*2+1][1],
           baseB + (sw_idx(row, ch) << 4));
    }
    #pragma unroll
    for (int mt = 0; mt < 4; mt++)
      #pragma unroll
      for (int nt = 0; nt < 8; nt++)
        mma_bf16(acc[mt][nt], afr[mt], bfr[nt]);
  }
}

// ---------------------------------------------------------------------------
// K0a: weights fp32 -> bf16 + alpha
// ---------------------------------------------------------------------------
__global__ void k_convert(const float* __restrict__ W1, const float* __restrict__ W2,
                          const float* __restrict__ alpha_raw){
  int t = blockIdx.x*blockDim.x + threadIdx.x;
  if (t == 0) g_alpha = log1pf(expf(alpha_raw[0]));
  if (t < HID*KDIM/4){
    float4 a = ((const float4*)W1)[t];
    float4 b = ((const float4*)W2)[t];
    uint2 pa, pb;
    *(__nv_bfloat162*)&pa.x = __floats2bfloat162_rn(a.x, a.y);
    *(__nv_bfloat162*)&pa.y = __floats2bfloat162_rn(a.z, a.w);
    *(__nv_bfloat162*)&pb.x = __floats2bfloat162_rn(b.x, b.y);
    *(__nv_bfloat162*)&pb.y = __floats2bfloat162_rn(b.z, b.w);
    ((uint2*)g_W1b)[t] = pa;
    ((uint2*)g_W2b)[t] = pb;
  }
}

// K0b: x fp32 -> bf16
__global__ void k_convx(const float* __restrict__ x){
  size_t t = (size_t)blockIdx.x*blockDim.x + threadIdx.x;
  if (t < TOT/4){
    float4 a = ((const float4*)x)[t];
    uint2 p;
    *(__nv_bfloat162*)&p.x = __floats2bfloat162_rn(a.x, a.y);
    *(__nv_bfloat162*)&p.y = __floats2bfloat162_rn(a.z, a.w);
    ((uint2*)g_xb)[t] = p;
  }
}

// ---------------------------------------------------------------------------
// K1: GEMM1 (implicit im2col, cp.async 4-stage) + bias + GELU -> G bf16
//     block 64(M) x 256(N), 128 threads (4 warps, 64x64 warp tiles), K=4096
// ---------------------------------------------------------------------------
__global__ void __launch_bounds__(128, 2) k_gemm1(const float* __restrict__ b1){
  extern __shared__ char dsm[];
  const uint32_t sbase = (uint32_t)__cvta_generic_to_shared(dsm);
  const int tid  = threadIdx.x;
  const int lane = tid & 31, warp = tid >> 5;   // warp = wn (0..3)
  const int l0 = blockIdx.x * 64;

  // A loader: thread -> row rr=tid>>1 (0..63), 2 chunks c in {(tid&1)*2, +1}
  const int rr = tid >> 1;
  const int c0 = (tid & 1) * 2;
  const int l = l0 + rr;
  const bool av = (l < M_TOT);
  const uint32_t asz = av ? 8u : 0u;
  int bb = 0, ph = 0, pw = 0;
  if (av){ bb = l / LPB; int rem = l - bb*LPB; ph = rem / NW; pw = rem - ph*NW; }
  const __nv_bfloat16* xb = g_xb + (size_t)bb*(NC*65536) + (size_t)(ph*4)*256 + pw*4;
  uint32_t adst[2];
  #pragma unroll
  for (int cc = 0; cc < 2; cc++) adst[cc] = (uint32_t)(sw_idx(rr, c0+cc) << 4);
  // B loader: thread -> rows rB=(tid>>2)+32q (q=0..7), chunk ch=tid&3
  const int rB = tid >> 2, ch = tid & 3;
  const __nv_bfloat16* bsrc = g_W1b + (size_t)rB*KDIM + ch*8;
  uint32_t bdst[8];
  #pragma unroll
  for (int q = 0; q < 8; q++) bdst[q] = 4096u + (uint32_t)(sw_idx(rB + 32*q, ch) << 4);

  const int KT = KDIM / 32;  // 128
  // prologue: stages 0..2
  #pragma unroll
  for (int kt = 0; kt < 3; kt++){
    uint32_t sb = sbase + (uint32_t)kt*STG;
    #pragma unroll
    for (int cc = 0; cc < 2; cc++){
      int k = kt*32 + (c0+cc)*8;
      const __nv_bfloat16* asrc = xb + (k >> 6)*65536 + ((k >> 3) & 7)*256;
      cpa8(sb + adst[cc],      asrc,     asz);
      cpa8(sb + adst[cc] + 8u, asrc + 4, asz);
    }
    #pragma unroll
    for (int q = 0; q < 8; q++) cpa16(sb + bdst[q], bsrc + (size_t)q*32*KDIM + kt*32, 16u);
    CP_COMMIT();
  }

  float acc[4][8][4];
  #pragma unroll
  for (int a = 0; a < 4; a++)
    #pragma unroll
    for (int b = 0; b < 8; b++)
      #pragma unroll
      for (int c = 0; c < 4; c++) acc[a][b][c] = 0.f;

  for (int kt = 0; kt < KT; kt++){
    if (kt + 2 < KT) CP_WAIT2(); else CP_WAIT0();
    __syncthreads();
    uint32_t sb = sbase + (uint32_t)(kt & 3)*STG;
    compute_tile(sb, sb + 4096u, warp, lane, acc);
    int kn = kt + 3;
    if (kn < KT){
      uint32_t sn = sbase + (uint32_t)(kn & 3)*STG;
      #pragma unroll
      for (int cc = 0; cc < 2; cc++){
        int k = kn*32 + (c0+cc)*8;
        const __nv_bfloat16* asrc = xb + (k >> 6)*65536 + ((k >> 3) & 7)*256;
        cpa8(sn + adst[cc],      asrc,     asz);
        cpa8(sn + adst[cc] + 8u, asrc + 4, asz);
      }
      #pragma unroll
      for (int q = 0; q < 8; q++) cpa16(sn + bdst[q], bsrc + (size_t)q*32*KDIM + kn*32, 16u);
      CP_COMMIT();
    }
  }

  // epilogue (direct, R11-proven form): bias + exact GELU -> g_G
  #pragma unroll
  for (int mt = 0; mt < 4; mt++){
    #pragma unroll
    for (int hf = 0; hf < 2; hf++){
      int r = mt*16 + (lane >> 2) + hf*8;
      size_t ll = (size_t)l0 + r;
      __nv_bfloat16* gp = g_G + ll*HID;
      #pragma unroll
      for (int nt = 0; nt < 8; nt++){
        int n = warp*64 + nt*8 + (lane & 3)*2;
        float v0 = acc[mt][nt][hf*2+0] + b1[n];
        float v1 = acc[mt][nt][hf*2+1] + b1[n+1];
        v0 = 0.5f*v0*(1.f + erff(v0*0.70710678118654752f));
        v1 = 0.5f*v1*(1.f + erff(v1*0.70710678118654752f));
        *(__nv_bfloat162*)(gp + n) = __floats2bfloat162_rn(v0, v1);
      }
    }
  }
}

// ---------------------------------------------------------------------------
// K2: GEMM2 (cp.async 4-stage) -> bias, direct scatter to 4 phase images
//     block 64(M) x 256(N of 4096), 128 threads, K=256
// ---------------------------------------------------------------------------
__global__ void __launch_bounds__(128, 2) k_gemm2(const float* __restrict__ b2){
  extern __shared__ char dsm[];
  const uint32_t sbase = (uint32_t)__cvta_generic_to_shared(dsm);
  const int tid  = threadIdx.x;
  const int lane = tid & 31, warp = tid >> 5;
  const int l0 = blockIdx.y * 64;
  const int n0 = blockIdx.x * 256;

  // A loader: row rr=tid>>1, 2 chunks (16B-aligned in g_G)
  const int rr = tid >> 1;
  const int c0 = (tid & 1) * 2;
  const __nv_bfloat16* ga = g_G + (size_t)(l0 + rr)*HID;   // rows < 16000 always valid
  uint32_t adst[2];
  #pragma unroll
  for (int cc = 0; cc < 2; cc++) adst[cc] = (uint32_t)(sw_idx(rr, c0+cc) << 4);
  // B loader
  const int rB = tid >> 2, ch = tid & 3;
  const __nv_bfloat16* bsrc = g_W2b + (size_t)(n0 + rB)*HID + ch*8;
  uint32_t bdst[8];
  #pragma unroll
  for (int q = 0; q < 8; q++) bdst[q] = 4096u + (uint32_t)(sw_idx(rB + 32*q, ch) << 4);

  const int KT = HID / 32;  // 8
  #pragma unroll
  for (int kt = 0; kt < 3; kt++){
    uint32_t sb = sbase + (uint32_t)kt*STG;
    #pragma unroll
    for (int cc = 0; cc < 2; cc++)
      cpa16(sb + adst[cc], ga + (c0+cc)*8 + kt*32, 16u);
    #pragma unroll
    for (int q = 0; q < 8; q++) cpa16(sb + bdst[q], bsrc + (size_t)q*32*HID + kt*32, 16u);
    CP_COMMIT();
  }

  float acc[4][8][4];
  #pragma unroll
  for (int a = 0; a < 4; a++)
    #pragma unroll
    for (int b = 0; b < 8; b++)
      #pragma unroll
      for (int c = 0; c < 4; c++) acc[a][b][c] = 0.f;

  for (int kt = 0; kt < KT; kt++){
    if (kt + 2 < KT) CP_WAIT2(); else CP_WAIT0();
    __syncthreads();
    uint32_t sb = sbase + (uint32_t)(kt & 3)*STG;
    compute_tile(sb, sb + 4096u, warp, lane, acc);
    int kn = kt + 3;
    if (kn < KT){
      uint32_t sn = sbase + (uint32_t)(kn & 3)*STG;
      #pragma unroll
      for (int cc = 0; cc < 2; cc++)
        cpa16(sn + adst[cc], ga + (c0+cc)*8 + kn*32, 16u);
      #pragma unroll
      for (int q = 0; q < 8; q++) cpa16(sn + bdst[q], bsrc + (size_t)q*32*HID + kn*32, 16u);
      CP_COMMIT();
    }
  }

  // epilogue (direct, R11-proven form): bias, scatter bf16x2 pairs into phase images
  #pragma unroll
  for (int mt = 0; mt < 4; mt++){
    #pragma unroll
    for (int hf = 0; hf < 2; hf++){
      int r = mt*16 + (lane >> 2) + hf*8;
      int l = l0 + r;
      if (l >= M_TOT) continue;
      int bb = l / LPB; int rem = l - bb*LPB;
      int ph = rem / NW; int pw = rem - ph*NW;
      #pragma unroll
      for (int nt = 0; nt < 8; nt++){
        int n  = n0 + warp*64 + nt*8 + (lane & 3)*2;
        int c  = n >> 6, kh = (n >> 3) & 7, kw = n & 7;  // kw pair shares phase
        int dlt = ((kh >> 2) << 1) | (kw >> 2);
        int i = ph*4 + kh;
        int j = pw*4 + kw;
        float v0 = acc[mt][nt][hf*2+0] + b2[n];
        float v1 = acc[mt][nt][hf*2+1] + b2[n+1];
        size_t idx = (((size_t)(dlt*NB + bb)*NC + c) << 16) + ((size_t)i << 8) + j;
        *(__nv_bfloat162*)(g_img + idx) = __floats2bfloat162_rn(v0, v1);
      }
    }
  }
}

// ---------------------------------------------------------------------------
// K3: blend  out = x + alpha * (sum of valid phase images)/norm  (x4 vectorized)
// ---------------------------------------------------------------------------
__global__ void k_blend(const float* __restrict__ x, float* __restrict__ out){
  size_t t = (size_t)blockIdx.x*blockDim.x + threadIdx.x;
  if (t >= TOT/4) return;
  size_t e = t*4;
  int j0 = (int)(e & 255);
  int i  = (int)((e >> 8) & 255);
  bool h0 = (i <= 251), h1 = (i >= 4), w0 = (j0 < 252), w1 = (j0 >= 4);

  float4 xv = *(const float4*)(x + e);
  float s0 = 0.f, s1 = 0.f, s2 = 0.f, s3 = 0.f;
  #pragma unroll
  for (int d = 0; d < 4; d++){
    bool v = (d == 0) ? (h0 && w0) : (d == 1) ? (h0 && w1) : (d == 2) ? (h1 && w0) : (h1 && w1);
    if (v){
      uint2 p = *(const uint2*)(g_img + (size_t)d*TOT + e);
      float2 f0 = __bfloat1622float2(*(const __nv_bfloat162*)&p.x);
      float2 f1 = __bfloat1622float2(*(const __nv_bfloat162*)&p.y);
      s0 += f0.x; s1 += f0.y; s2 += f1.x; s3 += f1.y;
    }
  }
  float scale = g_alpha * (((h0 && h1) ? 0.5f : 1.0f) * ((w0 && w1) ? 0.5f : 1.0f));
  float4 ov;
  ov.x = xv.x + scale * s0;
  ov.y = xv.y + scale * s1;
  ov.z = xv.z + scale * s2;
  ov.w = xv.w + scale * s3;
  *(float4*)(out + e) = ov;
}

// ---------------------------------------------------------------------------
extern "C" void kernel_launch(void* const* d_in, const int* in_sizes, int n_in,
                              void* d_out, int out_size){
  (void)in_sizes; (void)n_in; (void)out_size;
  const float* x         = (const float*)d_in[0];
  const float* W1        = (const float*)d_in[1];
  const float* b1        = (const float*)d_in[2];
  const float* W2        = (const float*)d_in[3];
  const float* b2        = (const float*)d_in[4];
  const float* alpha_raw = (const float*)d_in[5];
  float* out = (float*)d_out;

  // host-side attribute set (not an allocation; unconditional & deterministic)
  cudaFuncSetAttribute(k_gemm1, cudaFuncAttributeMaxDynamicSharedMemorySize, DSM);
  cudaFuncSetAttribute(k_gemm2, cudaFuncAttributeMaxDynamicSharedMemorySize, DSM);

  k_convert<<<(HID*KDIM/4 + 255)/256, 256>>>(W1, W2, alpha_raw);
  k_convx<<<(int)((TOT/4 + 255)/256), 256>>>(x);
  k_gemm1<<<250, 128, DSM>>>(b1);
  k_gemm2<<<dim3(16, 250), 128, DSM>>>(b2);
  k_blend<<<(int)((TOT/4 + 255)/256), 256>>>(x, out);
}